// round 8
// baseline (speedup 1.0000x reference)
#include <cuda_runtime.h>
#include <math.h>

// Problem constants (fixed by the dataset)
#define MM 512
#define NN 256
#define DD 64
#define EPSV 1e-6f
#define INFV 1e30f
#define SENTU 0xFFC00001u   // NaN payload; never produced by the DP arithmetic
#define FULLM 0xffffffffu

// ---------------- device scratch (no allocations allowed) ----------------
__device__ float g_dists[MM * NN];          // d[m][n]
__device__ float g_qT[NN * (NN + 1)];       // qT[nb][i] = q[i][nb]
__device__ float g_p[NN + 1];               // reachability
__device__ float g_w[NN * NN];              // w[n][nb] (0 where not an edge)
__device__ float g_fw[NN];                  // final weights p_back[N][:]
__device__ float g_C[MM * NN];              // DP table (sentinel-initialized)

// ---------------- tiny asm helpers ----------------
__device__ __forceinline__ unsigned ldcg_u32(const float* p) {
    unsigned v;
    asm volatile("ld.global.cg.b32 %0, [%1];" : "=r"(v) : "l"(p));
    return v;
}
__device__ __forceinline__ void stcg_f32(float* p, float v) {
    asm volatile("st.global.cg.b32 [%0], %1;" :: "l"(p), "f"(v));
}
// sum -> lane 0 (only lane 0 consumes the result)
__device__ __forceinline__ float warp_sum_to0(float v) {
    v += __shfl_down_sync(FULLM, v, 16);
    v += __shfl_down_sync(FULLM, v, 8);
    v += __shfl_down_sync(FULLM, v, 4);
    v += __shfl_down_sync(FULLM, v, 2);
    v += __shfl_down_sync(FULLM, v, 1);
    return v;
}

// ---------------- stage 0: fused sentinel-fill + q transpose ----------------
__global__ void __launch_bounds__(256) prep_kernel(const float* __restrict__ q) {
    int t = blockIdx.x * 256 + threadIdx.x;
    if (t < MM * NN) g_C[t] = __uint_as_float(SENTU);
    if (t < NN * (NN + 1)) {
        int nb = t / (NN + 1);
        int i  = t % (NN + 1);
        g_qT[t] = q[i * NN + nb];
    }
}

// ---------------- stage 1: pairwise L2 distances ----------
__global__ void __launch_bounds__(256) dist_kernel(const float* __restrict__ x,
                                                   const float* __restrict__ y) {
    __shared__ float xs[32][DD + 1];
    __shared__ float ys[64][DD + 1];
    int m0 = blockIdx.x * 32;
    int n0 = blockIdx.y * 64;
    int t = threadIdx.x;

    for (int i = t; i < 32 * DD; i += 256) xs[i / DD][i % DD] = x[(m0 + i / DD) * DD + i % DD];
    for (int i = t; i < 64 * DD; i += 256) ys[i / DD][i % DD] = y[(n0 + i / DD) * DD + i % DD];
    __syncthreads();

    int tn = t & 63;
    int tm = t >> 6;
    float acc[8];
#pragma unroll
    for (int r = 0; r < 8; r++) acc[r] = 0.f;

    for (int k = 0; k < DD; k++) {
        float yv = ys[tn][k];
#pragma unroll
        for (int r = 0; r < 8; r++) {
            float d = xs[tm * 8 + r][k] - yv;
            acc[r] = fmaf(d, d, acc[r]);
        }
    }
#pragma unroll
    for (int r = 0; r < 8; r++)
        g_dists[(m0 + tm * 8 + r) * NN + (n0 + tn)] = sqrtf(acc[r]);
}

// ---------------- stage 2: blocked forward-substitution reachability scan ---
__global__ void __launch_bounds__(256) scan_kernel() {
    __shared__ float sp[NN + 1];
    __shared__ float ps[32];
    int t = threadIdx.x;
    sp[t] = (t == 0) ? 1.f : 0.f;
    if (t == 0) sp[NN] = 0.f;
    __syncthreads();

    for (int blk = 0; blk < 8; blk++) {
        int base = blk * 32;
        if (t < 32) {
            float pl = sp[base + t];
#pragma unroll
            for (int s = 0; s < 32; s++) {
                float pnb = __shfl_sync(FULLM, pl, s);   // pre-update p[base+s]
                float qv = __ldg(&g_qT[(base + s) * (NN + 1) + base + t]);
                pl = fmaf(pnb, qv, pl);
                if (t == 0) ps[s] = pnb;
            }
            sp[base + t] = pl;
        }
        __syncthreads();
        if (t < 225) {
            int i = (t < base) ? t : t + 32;   // all elements outside the block
            float pi = sp[i];
#pragma unroll
            for (int s = 0; s < 32; s++)
                pi = fmaf(ps[s], __ldg(&g_qT[(base + s) * (NN + 1) + i]), pi);
            sp[i] = pi;
        }
        __syncthreads();
    }

    g_p[t] = sp[t];
    if (t == 0) g_p[NN] = sp[NN];
}

// ---------------- stage 3: mixing weights + terminal weights ---------------
__global__ void weights_kernel(const float* __restrict__ q) {
    int idx = blockIdx.x * 256 + threadIdx.x;  // N*N threads
    int n  = idx >> 8;
    int nb = idx & 255;
    float pb = g_p[nb] * q[n * NN + nb] / (g_p[n] + EPSV);
    g_w[idx] = (nb < n && pb > 0.f) ? pb : 0.f;
    if (n == 0) {
        g_fw[nb] = g_p[nb] * q[NN * NN + nb] / (g_p[NN] + EPSV);
    }
}

// ---------------- stage 4: pipelined fence-free wavefront DP ----------------
// One warp = one CTA = one column. Handoffs via sentinel-valued g_C in L2
// (st.cg / ld.cg). Software pipeline depth 2: rows m+1 and m+2 are in flight
// while row m is verified+computed, so the steady-state fast path never
// exposes L2 latency. Slow path (pipeline fill) is a TIGHT scalar spin on the
// boundary column n-1 — no __nanosleep (its ~us sleep quantum was the entire
// skew cost of rounds 4/7: 255 columns x ~2us fill skew ~ 600us). A spin on
// ld.global.cg self-throttles at one probe per L2 round trip and cannot
// starve the producer, which runs on a different SM (1 warp per CTA).
// After the boundary flips, one reload pass fixes any stale chunks: all
// columns < n-1 wrote row m before column n-1's value reached L2 (causality
// through the L2 point of coherence), so fresh loads must see them.
__global__ void __launch_bounds__(32, 16) dp_kernel() {
    const int lane = threadIdx.x;
    const int n = blockIdx.x;

    if (n == 0) {
        // column 0: C[m][0] = running sum of d[m][0] via warp inclusive scan
        float run = 0.f;
        for (int mb = 0; mb < MM; mb += 32) {
            float dv = g_dists[(mb + lane) * NN];
#pragma unroll
            for (int off = 1; off < 32; off <<= 1) {
                float t = __shfl_up_sync(FULLM, dv, off);
                if (lane >= off) dv += t;
            }
            float val = run + dv;
            stcg_f32(&g_C[(mb + lane) * NN], val);
            run = __shfl_sync(FULLM, val, 31);
        }
        return;
    }

    float wreg[8], Breg[8], Pprev[8];
#pragma unroll
    for (int j = 0; j < 8; j++) {
        int idx = j * 32 + lane;
        wreg[j]  = (idx < n) ? g_w[n * NN + idx] : 0.f;
        Breg[j]  = INFV;
        Pprev[j] = INFV;
    }

    const int jmax = (n - 1) >> 5;

    // prologue: issue loads for rows 0 and 1 (pipeline depth 2)
    unsigned cur[8], nxt[8], nx2[8];
#pragma unroll
    for (int j = 0; j < 8; j++) {
        if (j <= jmax) {
            cur[j] = ldcg_u32(&g_C[0 * NN + j * 32 + lane]);
            nxt[j] = ldcg_u32(&g_C[1 * NN + j * 32 + lane]);
        }
    }
    float dmn = __ldg(&g_dists[0 * NN + n]);
    float dn1 = __ldg(&g_dists[1 * NN + n]);
    float dn2 = 0.f;

    for (int m = 0; m < MM; m++) {
        // prefetch row m+2 (two rows of latency hiding)
        if (m + 2 < MM) {
#pragma unroll
            for (int j = 0; j < 8; j++)
                if (j <= jmax) nx2[j] = ldcg_u32(&g_C[(m + 2) * NN + j * 32 + lane]);
            dn2 = __ldg(&g_dists[(m + 2) * NN + n]);
        }

        // verify row m: fast path is one combined ballot
        {
            bool bad = false;
#pragma unroll
            for (int j = 0; j < 8; j++)
                if (j <= jmax) bad |= ((j * 32 + lane) < n) && (cur[j] == SENTU);
            if (__any_sync(FULLM, bad)) {
                const float* Crow = &g_C[m * NN];
                // tight scalar spin on boundary column n-1 (broadcast load)
                const float* pb = &Crow[n - 1];
                unsigned pv = ldcg_u32(pb);
                while (pv == SENTU) pv = ldcg_u32(pb);
                // single reload pass (guaranteed by L2 causality; loop kept
                // purely as a safety net — it exits after one iteration)
                for (;;) {
                    int again = 0;
#pragma unroll
                    for (int j = 0; j < 8; j++) {
                        if (j <= jmax) {
                            bool need = ((j * 32 + lane) < n) && (cur[j] == SENTU);
                            if (__any_sync(FULLM, need)) {
                                if (need) cur[j] = ldcg_u32(&Crow[j * 32 + lane]);
                                again = 1;
                            }
                        }
                    }
                    if (!again) break;
                }
            }
        }

        // compute cell (m, n)
        float acc = 0.f;
#pragma unroll
        for (int j = 0; j < 8; j++) {
            int idx = j * 32 + lane;
            if (idx < n) {
                float cc = __uint_as_float(cur[j]);
                float mn = fminf(cc, fminf(Pprev[j], Breg[j]));
                float cb = dmn + mn;
                if (wreg[j] > 0.f) { acc += wreg[j] * cb; Breg[j] = cb; }
                Pprev[j] = cc;
            }
        }
        acc = warp_sum_to0(acc);

        if (lane == 0) stcg_f32(&g_C[m * NN + n], acc);

        // rotate pipeline registers
#pragma unroll
        for (int j = 0; j < 8; j++) { cur[j] = nxt[j]; nxt[j] = nx2[j]; }
        dmn = dn1; dn1 = dn2;
    }
}

// ---------------- stage 5: terminal expectation ----------------------------
__global__ void __launch_bounds__(256) final_kernel(float* __restrict__ out) {
    int t = threadIdx.x;
    float v = g_fw[t] * g_C[(MM - 1) * NN + t];
#pragma unroll
    for (int off = 16; off; off >>= 1) v += __shfl_xor_sync(FULLM, v, off);
    __shared__ float s[8];
    if ((t & 31) == 0) s[t >> 5] = v;
    __syncthreads();
    if (t < 8) {
        float z = s[t];
#pragma unroll
        for (int off = 4; off; off >>= 1) z += __shfl_xor_sync(0xffu, z, off);
        if (t == 0) out[0] = z;
    }
}

// ---------------- launch ----------------------------------------------------
extern "C" void kernel_launch(void* const* d_in, const int* in_sizes, int n_in,
                              void* d_out, int out_size) {
    const float* x = nullptr;
    const float* y = nullptr;
    const float* q = nullptr;
    for (int i = 0; i < n_in; i++) {
        if (in_sizes[i] == MM * DD)            x = (const float*)d_in[i];
        else if (in_sizes[i] == NN * DD)       y = (const float*)d_in[i];
        else if (in_sizes[i] == (NN + 1) * NN) q = (const float*)d_in[i];
    }
    float* out = (float*)d_out;

    prep_kernel<<<(MM * NN + 255) / 256, 256>>>(q);

    dim3 dg(MM / 32, NN / 64);
    dist_kernel<<<dg, 256>>>(x, y);

    scan_kernel<<<1, 256>>>();
    weights_kernel<<<NN * NN / 256, 256>>>(q);

    dp_kernel<<<NN, 32>>>();    // one warp per column, one column per SM slot

    final_kernel<<<1, 256>>>(out);
}

// round 9
// speedup vs baseline: 1.5503x; 1.5503x over previous
#include <cuda_runtime.h>
#include <math.h>

// Problem constants (fixed by the dataset)
#define MM 512
#define NN 256
#define DD 64
#define EPSV 1e-6f
#define INFV 1e30f
#define SENTU 0xFFC00001u   // NaN payload; never produced by the DP arithmetic
#define FULLM 0xffffffffu
#define CPC 4               // columns per CTA = one warp per SMSP

// ---------------- device scratch (no allocations allowed) ----------------
__device__ float g_dists[MM * NN];          // d[m][n]
__device__ float g_qT[NN * (NN + 1)];       // qT[nb][i] = q[i][nb]
__device__ float g_p[NN + 1];               // reachability
__device__ float g_C[MM * NN];              // DP table (sentinel-initialized)

// ---------------- tiny asm helpers ----------------
__device__ __forceinline__ unsigned ldcg_u32(const float* p) {
    unsigned v;
    asm volatile("ld.global.cg.b32 %0, [%1];" : "=r"(v) : "l"(p));
    return v;
}
__device__ __forceinline__ void stcg_f32(float* p, float v) {
    asm volatile("st.global.cg.b32 [%0], %1;" :: "l"(p), "f"(v));
}
__device__ __forceinline__ unsigned long long lds_vol64(unsigned addr) {
    unsigned long long v;
    asm volatile("ld.volatile.shared.b64 %0, [%1];" : "=l"(v) : "r"(addr));
    return v;
}
__device__ __forceinline__ void sts_vol64(unsigned addr, unsigned long long v) {
    asm volatile("st.volatile.shared.b64 [%0], %1;" :: "r"(addr), "l"(v));
}
// sum -> lane 0 (only lane 0 consumes the result)
__device__ __forceinline__ float warp_sum_to0(float v) {
    v += __shfl_down_sync(FULLM, v, 16);
    v += __shfl_down_sync(FULLM, v, 8);
    v += __shfl_down_sync(FULLM, v, 4);
    v += __shfl_down_sync(FULLM, v, 2);
    v += __shfl_down_sync(FULLM, v, 1);
    return v;
}

// ---------------- stage 0: fused sentinel-fill + q transpose ----------------
__global__ void __launch_bounds__(256) prep_kernel(const float* __restrict__ q) {
    int t = blockIdx.x * 256 + threadIdx.x;
    if (t < MM * NN) g_C[t] = __uint_as_float(SENTU);
    if (t < NN * (NN + 1)) {
        int nb = t / (NN + 1);
        int i  = t % (NN + 1);
        g_qT[t] = q[i * NN + nb];
    }
}

// ---------------- stage 1: pairwise L2 distances ----------
__global__ void __launch_bounds__(256) dist_kernel(const float* __restrict__ x,
                                                   const float* __restrict__ y) {
    __shared__ float xs[32][DD + 1];
    __shared__ float ys[64][DD + 1];
    int m0 = blockIdx.x * 32;
    int n0 = blockIdx.y * 64;
    int t = threadIdx.x;

    for (int i = t; i < 32 * DD; i += 256) xs[i / DD][i % DD] = x[(m0 + i / DD) * DD + i % DD];
    for (int i = t; i < 64 * DD; i += 256) ys[i / DD][i % DD] = y[(n0 + i / DD) * DD + i % DD];
    __syncthreads();

    int tn = t & 63;
    int tm = t >> 6;
    float acc[8];
#pragma unroll
    for (int r = 0; r < 8; r++) acc[r] = 0.f;

    for (int k = 0; k < DD; k++) {
        float yv = ys[tn][k];
#pragma unroll
        for (int r = 0; r < 8; r++) {
            float d = xs[tm * 8 + r][k] - yv;
            acc[r] = fmaf(d, d, acc[r]);
        }
    }
#pragma unroll
    for (int r = 0; r < 8; r++)
        g_dists[(m0 + tm * 8 + r) * NN + (n0 + tn)] = sqrtf(acc[r]);
}

// ---------------- stage 2: blocked forward-substitution reachability scan ---
__global__ void __launch_bounds__(256) scan_kernel() {
    __shared__ float sp[NN + 1];
    __shared__ float ps[32];
    int t = threadIdx.x;
    sp[t] = (t == 0) ? 1.f : 0.f;
    if (t == 0) sp[NN] = 0.f;
    __syncthreads();

    for (int blk = 0; blk < 8; blk++) {
        int base = blk * 32;
        if (t < 32) {
            float pl = sp[base + t];
#pragma unroll
            for (int s = 0; s < 32; s++) {
                float pnb = __shfl_sync(FULLM, pl, s);   // pre-update p[base+s]
                float qv = __ldg(&g_qT[(base + s) * (NN + 1) + base + t]);
                pl = fmaf(pnb, qv, pl);
                if (t == 0) ps[s] = pnb;
            }
            sp[base + t] = pl;
        }
        __syncthreads();
        if (t < 225) {
            int i = (t < base) ? t : t + 32;   // all elements outside the block
            float pi = sp[i];
#pragma unroll
            for (int s = 0; s < 32; s++)
                pi = fmaf(ps[s], __ldg(&g_qT[(base + s) * (NN + 1) + i]), pi);
            sp[i] = pi;
        }
        __syncthreads();
    }

    g_p[t] = sp[t];
    if (t == 0) g_p[NN] = sp[NN];
}

// ---------------- stage 3: wavefront DP, 4 columns per CTA -----------------
// 64 CTAs x 4 warps; warp w (one per SMSP -> no arbiter contention, tight
// spins are starvation-free) owns column n = 4*cta + w.
// Intra-CTA handoff (3 of 4 hops): volatile 8B smem slot (row-tag, value),
// read at use time (~30cy) -> no prefetch-depth skew penalty.
// Inter-CTA handoff (1 of 4 hops): warp 0 spins on sentinel-valued
// C[m][base-1] in L2 and patches it into its chunk by broadcast.
// Earlier CTAs' columns: depth-2 prefetched ld.cg chunk loads + one-ballot
// verify; they are >=1 CTA-hop stale so the fast path nearly always hits.
// Deadlock-freedom: warp w waits only on own-CTA warps < w (smem) and global
// columns < base -> strict order over columns, induction from column 0.
__global__ void __launch_bounds__(128, 1) dp_kernel(const float* __restrict__ q) {
    __shared__ unsigned long long slot[MM * CPC];   // 16 KB
    const int lane = threadIdx.x & 31;
    const int w    = threadIdx.x >> 5;
    const int c    = blockIdx.x;
    const int base = c * CPC;
    const int n    = base + w;

    for (int i = threadIdx.x; i < MM * CPC; i += 128)
        slot[i] = 0xFFFFFFFF00000000ull;
    __syncthreads();
    const unsigned sbase = (unsigned)__cvta_generic_to_shared(slot);

    if (n == 0) {
        // column 0: running sum of d[m][0] via warp inclusive scan
        float run = 0.f;
        for (int mb = 0; mb < MM; mb += 32) {
            float dv = g_dists[(mb + lane) * NN];
#pragma unroll
            for (int off = 1; off < 32; off <<= 1) {
                float t = __shfl_up_sync(FULLM, dv, off);
                if (lane >= off) dv += t;
            }
            float val = run + dv;
            int m = mb + lane;
            stcg_f32(&g_C[m * NN], val);
            sts_vol64(sbase + (unsigned)(m * CPC) * 8u,
                      ((unsigned long long)(unsigned)m << 32) |
                      (unsigned long long)__float_as_uint(val));
            run = __shfl_sync(FULLM, val, 31);
        }
        return;
    }

    // per-column mixing weights computed in-place (replaces weights_kernel)
    float wreg[8], Breg[8], Pprev[8];
    float pn = g_p[n];
#pragma unroll
    for (int j = 0; j < 8; j++) {
        int idx = j * 32 + lane;
        float ww = 0.f;
        if (idx < n) {
            float pb = g_p[idx] * q[n * NN + idx] / (pn + EPSV);
            ww = (pb > 0.f) ? pb : 0.f;
        }
        wreg[j] = ww; Breg[j] = INFV; Pprev[j] = INFV;
    }

    const int jb = (base - 1) >> 5;      // last chunk holding global (< base) cols; -1 if none
    const int jq = base >> 5;            // chunk holding own-CTA columns
    const int lq = base & 31;
    const int lb = (base - 1) & 31;

    unsigned cur[8], nxt[8], nx2[8];
#pragma unroll
    for (int j = 0; j < 8; j++) { cur[j] = SENTU; nxt[j] = SENTU; nx2[j] = SENTU; }
#pragma unroll
    for (int j = 0; j < 8; j++) {
        if (j <= jb) {
            cur[j] = ldcg_u32(&g_C[0 * NN + j * 32 + lane]);
            nxt[j] = ldcg_u32(&g_C[1 * NN + j * 32 + lane]);
        }
    }
    float dmn = __ldg(&g_dists[0 * NN + n]);
    float dn1 = __ldg(&g_dists[1 * NN + n]);
    float dn2 = 0.f;

    for (int m = 0; m < MM; m++) {
        // prefetch row m+2 global chunks (earlier CTAs only)
        if (m + 2 < MM) {
#pragma unroll
            for (int j = 0; j < 8; j++)
                if (j <= jb) nx2[j] = ldcg_u32(&g_C[(m + 2) * NN + j * 32 + lane]);
            dn2 = __ldg(&g_dists[(m + 2) * NN + n]);
        }

        // own-CTA predecessors: tight smem spin (1 warp/SMSP -> safe)
        float patch = 0.f;
        if (w > 0) {
            unsigned saddr = sbase + (unsigned)(m * CPC + lane) * 8u;
            unsigned long long pk;
            for (;;) {
                pk = (lane < w) ? lds_vol64(saddr)
                               : ((unsigned long long)(unsigned)m << 32);
                if (__all_sync(FULLM, (unsigned)(pk >> 32) == (unsigned)m)) break;
            }
            patch = __uint_as_float((unsigned)pk);
        } else if (c > 0) {
            // CTA boundary: spin on column base-1 (scalar broadcast load)
            const float* pba = &g_C[m * NN + base - 1];
            unsigned bv = ldcg_u32(pba);
            while (bv == SENTU) bv = ldcg_u32(pba);
#pragma unroll
            for (int j = 0; j < 8; j++)
                if (j == jb && lane == lb) cur[j] = bv;   // patch by select
        }

        // verify global chunks (columns < base only; one-ballot fast path)
        {
            bool badp = false;
#pragma unroll
            for (int j = 0; j < 8; j++)
                if (j <= jb) badp |= ((j * 32 + lane) < base) && (cur[j] == SENTU);
            if (__any_sync(FULLM, badp)) {
                const float* Crow = &g_C[m * NN];
                for (;;) {
                    int again = 0;
#pragma unroll
                    for (int j = 0; j < 8; j++) {
                        if (j <= jb) {
                            bool need = ((j * 32 + lane) < base) && (cur[j] == SENTU);
                            if (__any_sync(FULLM, need)) {
                                if (need) cur[j] = ldcg_u32(&Crow[j * 32 + lane]);
                                again = 1;
                            }
                        }
                    }
                    if (!again) break;
                }
            }
        }

        // patch own-CTA columns into chunk jq via shfl
        if (w > 0) {
            int src = lane - lq;
            unsigned sh = __shfl_sync(FULLM, __float_as_uint(patch), src & 31);
            bool use = (src >= 0) && (src < w);
#pragma unroll
            for (int j = 0; j < 8; j++)
                if (j == jq && use) cur[j] = sh;
        }

        // compute cell (m, n)
        float acc = 0.f;
#pragma unroll
        for (int j = 0; j < 8; j++) {
            int idx = j * 32 + lane;
            if (idx < n) {
                float cc = __uint_as_float(cur[j]);
                float mn = fminf(cc, fminf(Pprev[j], Breg[j]));
                float cb = dmn + mn;
                if (wreg[j] > 0.f) { acc += wreg[j] * cb; Breg[j] = cb; }
                Pprev[j] = cc;
            }
        }
        acc = warp_sum_to0(acc);

        if (lane == 0) {
            stcg_f32(&g_C[m * NN + n], acc);
            sts_vol64(sbase + (unsigned)(m * CPC + w) * 8u,
                      ((unsigned long long)(unsigned)m << 32) |
                      (unsigned long long)__float_as_uint(acc));
        }

        // rotate pipeline registers
#pragma unroll
        for (int j = 0; j < 8; j++) { cur[j] = nxt[j]; nxt[j] = nx2[j]; }
        dmn = dn1; dn1 = dn2;
    }
}

// ---------------- stage 4: terminal expectation (weights fused in) ----------
__global__ void __launch_bounds__(256) final_kernel(const float* __restrict__ q,
                                                    float* __restrict__ out) {
    int t = threadIdx.x;
    float fw = g_p[t] * q[NN * NN + t] / (g_p[NN] + EPSV);
    float v = fw * g_C[(MM - 1) * NN + t];
#pragma unroll
    for (int off = 16; off; off >>= 1) v += __shfl_xor_sync(FULLM, v, off);
    __shared__ float s[8];
    if ((t & 31) == 0) s[t >> 5] = v;
    __syncthreads();
    if (t < 8) {
        float z = s[t];
#pragma unroll
        for (int off = 4; off; off >>= 1) z += __shfl_xor_sync(0xffu, z, off);
        if (t == 0) out[0] = z;
    }
}

// ---------------- launch ----------------------------------------------------
extern "C" void kernel_launch(void* const* d_in, const int* in_sizes, int n_in,
                              void* d_out, int out_size) {
    const float* x = nullptr;
    const float* y = nullptr;
    const float* q = nullptr;
    for (int i = 0; i < n_in; i++) {
        if (in_sizes[i] == MM * DD)            x = (const float*)d_in[i];
        else if (in_sizes[i] == NN * DD)       y = (const float*)d_in[i];
        else if (in_sizes[i] == (NN + 1) * NN) q = (const float*)d_in[i];
    }
    float* out = (float*)d_out;

    prep_kernel<<<(MM * NN + 255) / 256, 256>>>(q);       // launch 0

    dim3 dg(MM / 32, NN / 64);
    dist_kernel<<<dg, 256>>>(x, y);                        // launch 1

    scan_kernel<<<1, 256>>>();                             // launch 2

    dp_kernel<<<NN / CPC, CPC * 32>>>(q);                  // launch 3 (profiled slot)

    final_kernel<<<1, 256>>>(q, out);                      // launch 4
}